// round 6
// baseline (speedup 1.0000x reference)
#include <cuda_runtime.h>
#include <math.h>

#define BB 2
#define NN 512
#define CC 256
#define OUTSZ 14
#define SS 28                               // OUT * RATIO
#define POOL_PER_BOX (CC * OUTSZ * OUTSZ)   // 50176
#define NMS_THRC 0.5f

#define CG 8          // channels per shared-mem group
#define PSZ 448       // max patch floats per channel (analysis bound ~340)

// Scratch (no allocations allowed)
__device__ float g_verts[BB * NN * 4];
__device__ int   g_level[BB * NN];
__device__ int   g_keep [BB * NN];

// ---------------------------------------------------------------------------
// Kernel 1: per-batch NMS (bitmask greedy) + out_boxes/keep tail writes.
// One block of 512 threads per batch.
// ---------------------------------------------------------------------------
__global__ __launch_bounds__(NN) void nms_kernel(const float* __restrict__ boxes,
                                                 const float* __restrict__ scores,
                                                 float* __restrict__ out)
{
    const int b   = blockIdx.x;
    const int tid = threadIdx.x;

    __shared__ float skey[NN];
    __shared__ int   sidx[NN];
    __shared__ float bx1[NN], by1[NN], bx2[NN], by2[NN], barea[NN];
    __shared__ unsigned char slev[NN];
    __shared__ unsigned smask[NN][16];      // 32 KB suppression matrix
    __shared__ unsigned keepw_s[16];

    // --- verts + level ---
    const float* bbp = boxes + (size_t)b * NN * 4;
    float cx = bbp[tid * 4 + 0];
    float cy = bbp[tid * 4 + 1];
    float w  = bbp[tid * 4 + 2];
    float h  = bbp[tid * 4 + 3];
    float x1 = cx - w * 0.5f;
    float y1 = cy - h * 0.5f;
    float x2 = cx + w * 0.5f;
    float y2 = cy + h * 0.5f;

    float lv = floorf(3.0f + log2f(sqrtf(w * h) / 224.0f));
    lv = fminf(fmaxf(lv, 1.0f), 4.0f);
    int lev = (int)lv;

    int gi = b * NN + tid;
    g_verts[gi * 4 + 0] = x1;
    g_verts[gi * 4 + 1] = y1;
    g_verts[gi * 4 + 2] = x2;
    g_verts[gi * 4 + 3] = y2;
    g_level[gi] = lev;

    skey[tid] = scores[gi];
    sidx[tid] = tid;
    __syncthreads();

    // --- bitonic sort: descending score, ties by ascending original idx ---
    for (int k = 2; k <= NN; k <<= 1) {
        for (int j = k >> 1; j > 0; j >>= 1) {
            int ixj = tid ^ j;
            if (ixj > tid) {
                float sa = skey[tid], sb2 = skey[ixj];
                int   ia = sidx[tid], ib  = sidx[ixj];
                bool a_first = (sa > sb2) || (sa == sb2 && ia < ib);
                bool ascending = ((tid & k) == 0);
                bool do_swap = ascending ? (!a_first) : a_first;
                if (do_swap) {
                    skey[tid] = sb2; skey[ixj] = sa;
                    sidx[tid] = ib;  sidx[ixj] = ia;
                }
            }
            __syncthreads();
        }
    }

    // --- load sorted boxes into shared ---
    int o  = sidx[tid];
    int go = b * NN + o;
    float sx1 = g_verts[go * 4 + 0];
    float sy1 = g_verts[go * 4 + 1];
    float sx2 = g_verts[go * 4 + 2];
    float sy2 = g_verts[go * 4 + 3];
    bx1[tid] = sx1; by1[tid] = sy1; bx2[tid] = sx2; by2[tid] = sy2;
    float marea = (sx2 - sx1) * (sy2 - sy1);
    barea[tid] = marea;
    slev[tid]  = (unsigned char)g_level[go];
    __syncthreads();

    // --- build suppression row for this (sorted) rank ---
    {
        int myw = tid >> 5;
        unsigned char mylev = slev[tid];
        for (int wq = 0; wq < myw; wq++) smask[tid][wq] = 0u;
        for (int wq = myw; wq < 16; wq++) {
            unsigned bits = 0u;
            #pragma unroll
            for (int jb = 0; jb < 32; jb++) {
                int j = (wq << 5) + jb;
                float ix1 = fmaxf(sx1, bx1[j]);   // broadcast LDS across warp
                float iy1 = fmaxf(sy1, by1[j]);
                float ix2 = fminf(sx2, bx2[j]);
                float iy2 = fminf(sy2, by2[j]);
                float iw = fmaxf(ix2 - ix1, 0.0f);
                float ih = fmaxf(iy2 - iy1, 0.0f);
                float inter = iw * ih;
                float iou = inter / (marea + barea[j] - inter + 1e-9f);
                bool sup = (j > tid) && (slev[j] == mylev) && (iou > NMS_THRC);
                bits |= ((unsigned)sup) << jb;
            }
            smask[tid][wq] = bits;
        }
    }
    __syncthreads();

    // --- greedy scan (single warp; lanes hold keep-bit words) ---
    if (tid < 32) {
        int wl = tid & 15;
        unsigned kw = 0xFFFFFFFFu;
        #pragma unroll 1
        for (int wq = 0; wq < 16; wq++) {
            unsigned cur = __shfl_sync(0xffffffffu, kw, wq);
            #pragma unroll 1
            for (int bq = 0; bq < 32; bq++) {
                if ((cur >> bq) & 1u) {
                    const unsigned* mrow = smask[(wq << 5) + bq];
                    cur &= ~mrow[wq];
                    kw  &= ~mrow[wl];
                }
            }
        }
        if (tid < 16) keepw_s[tid] = kw;
    }
    __syncthreads();

    int kept = (keepw_s[tid >> 5] >> (tid & 31)) & 1;
    g_keep[go] = kept;

    // --- fused tail: out_boxes + keep ---
    float* ob = out + (size_t)BB * NN * POOL_PER_BOX;
    float* ok = ob + (size_t)BB * NN * 4;
    ob[go * 4 + 0] = kept ? sx1 : 0.0f;
    ob[go * 4 + 1] = kept ? sy1 : 0.0f;
    ob[go * 4 + 2] = kept ? sx2 : 0.0f;
    ob[go * 4 + 3] = kept ? sy2 : 0.0f;
    ok[go] = kept ? 1.0f : 0.0f;
}

// ---------------------------------------------------------------------------
// Kernel 2: ROI align via shared-memory feature patch.
// One 256-thread block per (b, n) box.
// ---------------------------------------------------------------------------
__global__ __launch_bounds__(256) void pool_kernel(const float* __restrict__ p4,
                                                   const float* __restrict__ p8,
                                                   const float* __restrict__ p16,
                                                   const float* __restrict__ p32,
                                                   float* __restrict__ out)
{
    const int bn  = blockIdx.x;
    const int b   = bn / NN;
    const int tid = threadIdx.x;

    float* o = out + (size_t)bn * POOL_PER_BOX;

    if (!g_keep[bn]) {
        float4* o4 = (float4*)o;
        float4 z = make_float4(0.f, 0.f, 0.f, 0.f);
        #pragma unroll 4
        for (int i = tid; i < POOL_PER_BOX / 4; i += 256) o4[i] = z;
        return;
    }

    const int lev = g_level[bn];
    const float* feat;
    int H;
    float stride;
    if (lev == 1)      { feat = p4;  H = 256; stride = 4.0f;  }
    else if (lev == 2) { feat = p8;  H = 128; stride = 8.0f;  }
    else if (lev == 3) { feat = p16; H = 64;  stride = 16.0f; }
    else               { feat = p32; H = 32;  stride = 32.0f; }
    const int W = H;
    const int HW = H * W;

    __shared__ int   sxi0[SS], sxi1[SS];       // col indices (patch-relative)
    __shared__ int   syo0[SS], syo1[SS];       // row offsets (pre-multiplied by pitch)
    __shared__ float slx[SS], sly[SS];
    __shared__ float patch[CG * PSZ];

    // ROI in feature coords
    float rx1 = g_verts[bn * 4 + 0] / stride;
    float ry1 = g_verts[bn * 4 + 1] / stride;
    float rx2 = g_verts[bn * 4 + 2] / stride;
    float ry2 = g_verts[bn * 4 + 3] / stride;
    float bw = (rx2 - rx1) / (float)OUTSZ;
    float bh = (ry2 - ry1) / (float)OUTSZ;

    // Phase 1: absolute sample tables
    if (tid < SS) {
        float g = ((float)tid + 0.5f) * 0.5f;
        float xs = fminf(fmaxf(rx1 + g * bw, 0.0f), (float)W - 1.0f);
        float x0 = floorf(xs);
        int x0i = (int)x0;
        sxi0[tid] = x0i;
        sxi1[tid] = min(x0i + 1, W - 1);
        slx[tid]  = xs - x0;
    } else if (tid < 2 * SS) {
        int t = tid - SS;
        float g = ((float)t + 0.5f) * 0.5f;
        float ys = fminf(fmaxf(ry1 + g * bh, 0.0f), (float)H - 1.0f);
        float y0 = floorf(ys);
        int y0i = (int)y0;
        syo0[t] = y0i;
        syo1[t] = min(y0i + 1, H - 1);
        sly[t]  = ys - y0;
    }
    __syncthreads();

    // Patch bounds (tables are monotonic non-decreasing)
    const int xmin  = sxi0[0];
    const int pcols = sxi1[SS - 1] - xmin + 1;
    const int ymin  = syo0[0];
    const int prows = syo1[SS - 1] - ymin + 1;
    const int pp    = prows * pcols;
    const bool use_smem = (pp <= PSZ);
    const int pitch = use_smem ? pcols : W;
    __syncthreads();

    // Phase 2: make tables patch-relative; pre-multiply row offsets by pitch
    if (tid < SS) {
        sxi0[tid] -= xmin;
        sxi1[tid] -= xmin;
    } else if (tid < 2 * SS) {
        int t = tid - SS;
        syo0[t] = (syo0[t] - ymin) * pitch;
        syo1[t] = (syo1[t] - ymin) * pitch;
    }
    __syncthreads();

    // Base so that relative coords work in both smem and gmem modes
    const float* fb = feat + (size_t)b * CC * HW + (size_t)ymin * W + xmin;

    const int wid  = tid >> 5;
    const int lane = tid & 31;

    for (int c0 = 0; c0 < CC; c0 += CG) {
        if (use_smem) {
            #pragma unroll
            for (int ch = 0; ch < CG; ch++) {
                const float* fc = fb + (size_t)(c0 + ch) * HW;
                float* pch = patch + ch * PSZ;
                for (int py = wid; py < prows; py += 8)
                    for (int px = lane; px < pcols; px += 32)
                        pch[py * pcols + px] = __ldg(fc + py * W + px);
            }
            __syncthreads();
        }

        for (int idx = tid; idx < CG * (OUTSZ * OUTSZ); idx += 256) {
            int ch  = idx / (OUTSZ * OUTSZ);
            int pos = idx - ch * (OUTSZ * OUTSZ);
            int oy  = pos / OUTSZ;
            int ox  = pos - oy * OUTSZ;

            const float* P = use_smem ? (patch + ch * PSZ)
                                      : (fb + (size_t)(c0 + ch) * HW);
            float acc = 0.0f;
            #pragma unroll
            for (int dy = 0; dy < 2; dy++) {
                int yy = 2 * oy + dy;
                int a0 = syo0[yy], a1 = syo1[yy];
                float ly = sly[yy];
                #pragma unroll
                for (int dx = 0; dx < 2; dx++) {
                    int xx = 2 * ox + dx;
                    int x0 = sxi0[xx], x1 = sxi1[xx];
                    float lx = slx[xx];
                    float v00 = P[a0 + x0];
                    float v01 = P[a0 + x1];
                    float v10 = P[a1 + x0];
                    float v11 = P[a1 + x1];
                    float h0 = fmaf(lx, v01 - v00, v00);
                    float h1 = fmaf(lx, v11 - v10, v10);
                    acc += fmaf(ly, h1 - h0, h0);
                }
            }
            o[(c0 + ch) * (OUTSZ * OUTSZ) + pos] = acc * 0.25f;
        }
        if (use_smem) __syncthreads();
    }
}

extern "C" void kernel_launch(void* const* d_in, const int* in_sizes, int n_in,
                              void* d_out, int out_size)
{
    const float* p4     = (const float*)d_in[0];
    const float* p8     = (const float*)d_in[1];
    const float* p16    = (const float*)d_in[2];
    const float* p32    = (const float*)d_in[3];
    const float* boxes  = (const float*)d_in[4];
    const float* scores = (const float*)d_in[5];
    float* out = (float*)d_out;

    nms_kernel<<<BB, NN>>>(boxes, scores, out);
    pool_kernel<<<BB * NN, 256>>>(p4, p8, p16, p32, out);
}

// round 7
// speedup vs baseline: 3.5840x; 3.5840x over previous
#include <cuda_runtime.h>
#include <math.h>

#define BB 2
#define NN 512
#define CC 256
#define OUTSZ 14
#define POOL_PER_BOX (CC * OUTSZ * OUTSZ)   // 50176
#define NPOS (OUTSZ * OUTSZ)                // 196
#define NMS_THRC 0.5f

// Scratch (no allocations allowed)
__device__ float g_verts[BB * NN * 4];
__device__ int   g_level[BB * NN];
__device__ int   g_keep [BB * NN];

// ---------------------------------------------------------------------------
// Kernel 1: per-batch NMS (bitmask greedy) + out_boxes/keep tail writes.
// One block of 512 threads per batch.  (Known-good from R6 bench.)
// ---------------------------------------------------------------------------
__global__ __launch_bounds__(NN) void nms_kernel(const float* __restrict__ boxes,
                                                 const float* __restrict__ scores,
                                                 float* __restrict__ out)
{
    const int b   = blockIdx.x;
    const int tid = threadIdx.x;

    __shared__ float skey[NN];
    __shared__ int   sidx[NN];
    __shared__ float bx1[NN], by1[NN], bx2[NN], by2[NN], barea[NN];
    __shared__ unsigned char slev[NN];
    __shared__ unsigned smask[NN][16];      // 32 KB suppression matrix
    __shared__ unsigned keepw_s[16];

    // --- verts + level ---
    const float* bbp = boxes + (size_t)b * NN * 4;
    float cx = bbp[tid * 4 + 0];
    float cy = bbp[tid * 4 + 1];
    float w  = bbp[tid * 4 + 2];
    float h  = bbp[tid * 4 + 3];
    float x1 = cx - w * 0.5f;
    float y1 = cy - h * 0.5f;
    float x2 = cx + w * 0.5f;
    float y2 = cy + h * 0.5f;

    float lv = floorf(3.0f + log2f(sqrtf(w * h) / 224.0f));
    lv = fminf(fmaxf(lv, 1.0f), 4.0f);
    int lev = (int)lv;

    int gi = b * NN + tid;
    g_verts[gi * 4 + 0] = x1;
    g_verts[gi * 4 + 1] = y1;
    g_verts[gi * 4 + 2] = x2;
    g_verts[gi * 4 + 3] = y2;
    g_level[gi] = lev;

    skey[tid] = scores[gi];
    sidx[tid] = tid;
    __syncthreads();

    // --- bitonic sort: descending score, ties by ascending original idx ---
    for (int k = 2; k <= NN; k <<= 1) {
        for (int j = k >> 1; j > 0; j >>= 1) {
            int ixj = tid ^ j;
            if (ixj > tid) {
                float sa = skey[tid], sb2 = skey[ixj];
                int   ia = sidx[tid], ib  = sidx[ixj];
                bool a_first = (sa > sb2) || (sa == sb2 && ia < ib);
                bool ascending = ((tid & k) == 0);
                bool do_swap = ascending ? (!a_first) : a_first;
                if (do_swap) {
                    skey[tid] = sb2; skey[ixj] = sa;
                    sidx[tid] = ib;  sidx[ixj] = ia;
                }
            }
            __syncthreads();
        }
    }

    // --- load sorted boxes into shared ---
    int o  = sidx[tid];
    int go = b * NN + o;
    float sx1 = g_verts[go * 4 + 0];
    float sy1 = g_verts[go * 4 + 1];
    float sx2 = g_verts[go * 4 + 2];
    float sy2 = g_verts[go * 4 + 3];
    bx1[tid] = sx1; by1[tid] = sy1; bx2[tid] = sx2; by2[tid] = sy2;
    float marea = (sx2 - sx1) * (sy2 - sy1);
    barea[tid] = marea;
    slev[tid]  = (unsigned char)g_level[go];
    __syncthreads();

    // --- build suppression row for this (sorted) rank ---
    {
        int myw = tid >> 5;
        unsigned char mylev = slev[tid];
        for (int wq = 0; wq < myw; wq++) smask[tid][wq] = 0u;
        for (int wq = myw; wq < 16; wq++) {
            unsigned bits = 0u;
            #pragma unroll
            for (int jb = 0; jb < 32; jb++) {
                int j = (wq << 5) + jb;
                float ix1 = fmaxf(sx1, bx1[j]);
                float iy1 = fmaxf(sy1, by1[j]);
                float ix2 = fminf(sx2, bx2[j]);
                float iy2 = fminf(sy2, by2[j]);
                float iw = fmaxf(ix2 - ix1, 0.0f);
                float ih = fmaxf(iy2 - iy1, 0.0f);
                float inter = iw * ih;
                float iou = inter / (marea + barea[j] - inter + 1e-9f);
                bool sup = (j > tid) && (slev[j] == mylev) && (iou > NMS_THRC);
                bits |= ((unsigned)sup) << jb;
            }
            smask[tid][wq] = bits;
        }
    }
    __syncthreads();

    // --- greedy scan (single warp; lanes hold keep-bit words) ---
    if (tid < 32) {
        int wl = tid & 15;
        unsigned kw = 0xFFFFFFFFu;
        #pragma unroll 1
        for (int wq = 0; wq < 16; wq++) {
            unsigned cur = __shfl_sync(0xffffffffu, kw, wq);
            #pragma unroll 1
            for (int bq = 0; bq < 32; bq++) {
                if ((cur >> bq) & 1u) {
                    const unsigned* mrow = smask[(wq << 5) + bq];
                    cur &= ~mrow[wq];
                    kw  &= ~mrow[wl];
                }
            }
        }
        if (tid < 16) keepw_s[tid] = kw;
    }
    __syncthreads();

    int kept = (keepw_s[tid >> 5] >> (tid & 31)) & 1;
    g_keep[go] = kept;

    // --- fused tail: out_boxes + keep ---
    float* ob = out + (size_t)BB * NN * POOL_PER_BOX;
    float* ok = ob + (size_t)BB * NN * 4;
    ob[go * 4 + 0] = kept ? sx1 : 0.0f;
    ob[go * 4 + 1] = kept ? sy1 : 0.0f;
    ob[go * 4 + 2] = kept ? sx2 : 0.0f;
    ob[go * 4 + 3] = kept ? sy2 : 0.0f;
    ok[go] = kept ? 1.0f : 0.0f;
}

// ---------------------------------------------------------------------------
// Kernel 2: ROI align. One 256-thread block per box; thread t < 196 owns one
// output position. 16 tap offsets + 8 weights live in registers; inner loop
// marches over 256 channels with pure __ldg gathers and coalesced stores.
// ---------------------------------------------------------------------------
__global__ __launch_bounds__(256) void pool_kernel(const float* __restrict__ p4,
                                                   const float* __restrict__ p8,
                                                   const float* __restrict__ p16,
                                                   const float* __restrict__ p32,
                                                   float* __restrict__ out)
{
    const int bn  = blockIdx.x;
    const int b   = bn / NN;
    const int tid = threadIdx.x;

    float* o = out + (size_t)bn * POOL_PER_BOX;

    if (!g_keep[bn]) {
        float4* o4 = (float4*)o;
        float4 z = make_float4(0.f, 0.f, 0.f, 0.f);
        #pragma unroll 4
        for (int i = tid; i < POOL_PER_BOX / 4; i += 256) o4[i] = z;
        return;
    }
    if (tid >= NPOS) return;

    const int lev = g_level[bn];
    const float* feat;
    int H;
    float stride;
    if (lev == 1)      { feat = p4;  H = 256; stride = 4.0f;  }
    else if (lev == 2) { feat = p8;  H = 128; stride = 8.0f;  }
    else if (lev == 3) { feat = p16; H = 64;  stride = 16.0f; }
    else               { feat = p32; H = 32;  stride = 32.0f; }
    const int W  = H;
    const int HW = H * W;

    // ROI in feature coords
    float inv = 1.0f / stride;
    float rx1 = g_verts[bn * 4 + 0] * inv;
    float ry1 = g_verts[bn * 4 + 1] * inv;
    float rx2 = g_verts[bn * 4 + 2] * inv;
    float ry2 = g_verts[bn * 4 + 3] * inv;
    float bw = (rx2 - rx1) / (float)OUTSZ;
    float bh = (ry2 - ry1) / (float)OUTSZ;

    const int oy = tid / OUTSZ;
    const int ox = tid - oy * OUTSZ;

    // 4 col offsets + weights (two x-samples, two taps each)
    int   cofs[4];
    float wx[4];
    #pragma unroll
    for (int j = 0; j < 2; j++) {
        float g  = ((float)(2 * ox + j) + 0.5f) * 0.5f;
        float xs = fminf(fmaxf(rx1 + g * bw, 0.0f), (float)W - 1.0f);
        float x0f = floorf(xs);
        int   x0  = (int)x0f;
        float lx  = xs - x0f;
        cofs[2 * j]     = x0;
        cofs[2 * j + 1] = min(x0 + 1, W - 1);
        wx[2 * j]       = 1.0f - lx;
        wx[2 * j + 1]   = lx;
    }
    // 4 row offsets + weights
    int   rofs[4];
    float wy[4];
    #pragma unroll
    for (int j = 0; j < 2; j++) {
        float g  = ((float)(2 * oy + j) + 0.5f) * 0.5f;
        float ys = fminf(fmaxf(ry1 + g * bh, 0.0f), (float)H - 1.0f);
        float y0f = floorf(ys);
        int   y0  = (int)y0f;
        float ly  = ys - y0f;
        rofs[2 * j]     = y0 * W;
        rofs[2 * j + 1] = min(y0 + 1, H - 1) * W;
        wy[2 * j]       = 1.0f - ly;
        wy[2 * j + 1]   = ly;
    }

    // 16 combined tap offsets (cross product)
    int off[16];
    #pragma unroll
    for (int k = 0; k < 4; k++)
        #pragma unroll
        for (int l = 0; l < 4; l++)
            off[k * 4 + l] = rofs[k] + cofs[l];

    const float* fp = feat + (size_t)b * CC * HW;
    float* op = o + tid;

    #pragma unroll 2
    for (int c = 0; c < CC; c++) {
        float acc = 0.0f;
        #pragma unroll
        for (int k = 0; k < 4; k++) {
            float v0 = __ldg(fp + off[k * 4 + 0]);
            float v1 = __ldg(fp + off[k * 4 + 1]);
            float v2 = __ldg(fp + off[k * 4 + 2]);
            float v3 = __ldg(fp + off[k * 4 + 3]);
            float hsum = wx[0] * v0;
            hsum = fmaf(wx[1], v1, hsum);
            hsum = fmaf(wx[2], v2, hsum);
            hsum = fmaf(wx[3], v3, hsum);
            acc  = fmaf(wy[k], hsum, acc);
        }
        op[c * NPOS] = acc * 0.25f;
        fp += HW;
    }
}

extern "C" void kernel_launch(void* const* d_in, const int* in_sizes, int n_in,
                              void* d_out, int out_size)
{
    const float* p4     = (const float*)d_in[0];
    const float* p8     = (const float*)d_in[1];
    const float* p16    = (const float*)d_in[2];
    const float* p32    = (const float*)d_in[3];
    const float* boxes  = (const float*)d_in[4];
    const float* scores = (const float*)d_in[5];
    float* out = (float*)d_out;

    nms_kernel<<<BB, NN>>>(boxes, scores, out);
    pool_kernel<<<BB * NN, 256>>>(p4, p8, p16, p32, out);
}

// round 8
// speedup vs baseline: 3.9597x; 1.1048x over previous
#include <cuda_runtime.h>
#include <math.h>

#define BB 2
#define NN 512
#define CC 256
#define OUTSZ 14
#define POOL_PER_BOX (CC * OUTSZ * OUTSZ)   // 50176
#define NPOS (OUTSZ * OUTSZ)                // 196
#define NMS_THRC 0.5f

// Scratch (no allocations allowed)
__device__ float  g_verts[BB * NN * 4];     // original order
__device__ int    g_level[BB * NN];         // original order
__device__ int    g_keep [BB * NN];         // original order
__device__ float4 gs_box [BB * NN];         // sorted order (x1,y1,x2,y2)
__device__ float  gs_area[BB * NN];
__device__ int    gs_lev [BB * NN];
__device__ int    gs_ord [BB * NN];         // sorted rank -> original index
__device__ unsigned g_mask[BB * NN * 16];   // suppression matrix (sorted order)

// ---------------------------------------------------------------------------
// Kernel A: verts + level + stable sort by (-score, idx). Grid=BB, 512 thr.
// ---------------------------------------------------------------------------
__global__ __launch_bounds__(NN) void nms_sort_kernel(const float* __restrict__ boxes,
                                                      const float* __restrict__ scores)
{
    const int b   = blockIdx.x;
    const int tid = threadIdx.x;

    __shared__ float skey[NN];
    __shared__ int   sidx[NN];

    const float* bbp = boxes + (size_t)b * NN * 4;
    float cx = bbp[tid * 4 + 0];
    float cy = bbp[tid * 4 + 1];
    float w  = bbp[tid * 4 + 2];
    float h  = bbp[tid * 4 + 3];
    float x1 = cx - w * 0.5f;
    float y1 = cy - h * 0.5f;
    float x2 = cx + w * 0.5f;
    float y2 = cy + h * 0.5f;

    float lv = floorf(3.0f + log2f(sqrtf(w * h) / 224.0f));
    lv = fminf(fmaxf(lv, 1.0f), 4.0f);
    int lev = (int)lv;

    int gi = b * NN + tid;
    g_verts[gi * 4 + 0] = x1;
    g_verts[gi * 4 + 1] = y1;
    g_verts[gi * 4 + 2] = x2;
    g_verts[gi * 4 + 3] = y2;
    g_level[gi] = lev;

    skey[tid] = scores[gi];
    sidx[tid] = tid;
    __syncthreads();

    // bitonic sort: descending score, ties by ascending original idx
    for (int k = 2; k <= NN; k <<= 1) {
        for (int j = k >> 1; j > 0; j >>= 1) {
            int ixj = tid ^ j;
            if (ixj > tid) {
                float sa = skey[tid], sb2 = skey[ixj];
                int   ia = sidx[tid], ib  = sidx[ixj];
                bool a_first = (sa > sb2) || (sa == sb2 && ia < ib);
                bool ascending = ((tid & k) == 0);
                bool do_swap = ascending ? (!a_first) : a_first;
                if (do_swap) {
                    skey[tid] = sb2; skey[ixj] = sa;
                    sidx[tid] = ib;  sidx[ixj] = ia;
                }
            }
            __syncthreads();
        }
    }

    int o  = sidx[tid];
    int go = b * NN + o;
    float sx1 = g_verts[go * 4 + 0];
    float sy1 = g_verts[go * 4 + 1];
    float sx2 = g_verts[go * 4 + 2];
    float sy2 = g_verts[go * 4 + 3];
    int gr = b * NN + tid;
    gs_box [gr] = make_float4(sx1, sy1, sx2, sy2);
    gs_area[gr] = (sx2 - sx1) * (sy2 - sy1);
    gs_lev [gr] = g_level[go];
    gs_ord [gr] = o;
}

// ---------------------------------------------------------------------------
// Kernel B: suppression-matrix build. Grid = BB*4 blocks x 128 threads;
// each thread owns one sorted row (interleaved for balance).
// ---------------------------------------------------------------------------
__global__ __launch_bounds__(128) void nms_mask_kernel()
{
    const int b   = blockIdx.x >> 2;
    const int sub = blockIdx.x & 3;

    __shared__ float4        sbox[NN];
    __shared__ float         sarea[NN];
    __shared__ unsigned char slev[NN];

    for (int i = threadIdx.x; i < NN; i += 128) {
        int g = b * NN + i;
        sbox[i]  = gs_box[g];
        sarea[i] = gs_area[g];
        slev[i]  = (unsigned char)gs_lev[g];
    }
    __syncthreads();

    const int r = threadIdx.x * 4 + sub;      // 0..511, interleaved
    float4 mb = sbox[r];
    float  marea = sarea[r];
    unsigned char mylev = slev[r];
    const int myw = r >> 5;

    unsigned* mrow = g_mask + ((size_t)b * NN + r) * 16;
    for (int wq = 0; wq < myw; wq++) mrow[wq] = 0u;
    for (int wq = myw; wq < 16; wq++) {
        unsigned bits = 0u;
        #pragma unroll
        for (int jb = 0; jb < 32; jb++) {
            int j = (wq << 5) + jb;
            float4 ob = sbox[j];
            float ix1 = fmaxf(mb.x, ob.x);
            float iy1 = fmaxf(mb.y, ob.y);
            float ix2 = fminf(mb.z, ob.z);
            float iy2 = fminf(mb.w, ob.w);
            float iw = fmaxf(ix2 - ix1, 0.0f);
            float ih = fmaxf(iy2 - iy1, 0.0f);
            float inter = iw * ih;
            float iou = inter / (marea + sarea[j] - inter + 1e-9f);
            bool sup = (j > r) && (slev[j] == mylev) && (iou > NMS_THRC);
            bits |= ((unsigned)sup) << jb;
        }
        mrow[wq] = bits;
    }
}

// ---------------------------------------------------------------------------
// Kernel C: greedy scan (ffs-skip over kept boxes) + keep/tail writes.
// Grid = BB, 512 threads.
// ---------------------------------------------------------------------------
__global__ __launch_bounds__(NN) void nms_scan_kernel(float* __restrict__ out)
{
    const int b   = blockIdx.x;
    const int tid = threadIdx.x;

    __shared__ unsigned smask[NN][16];
    __shared__ unsigned keepw_s[16];

    // stage matrix into shared (vectorized)
    {
        const uint4* src = (const uint4*)(g_mask + (size_t)b * NN * 16);
        uint4* dst = (uint4*)smask;
        #pragma unroll
        for (int i = tid; i < NN * 4; i += NN) dst[i] = src[i];
    }
    __syncthreads();

    if (tid < 32) {
        int wl = tid & 15;
        unsigned kw = 0xFFFFFFFFu;
        for (int wq = 0; wq < 16; wq++) {
            unsigned cur = __shfl_sync(0xffffffffu, kw, wq);
            while (cur) {
                int bq = __ffs(cur) - 1;
                int row = (wq << 5) + bq;
                unsigned mw = smask[row][wl];   // broadcast LDS
                unsigned mq = smask[row][wq];   // broadcast LDS
                cur &= ~(mq | (1u << bq));
                kw  &= ~mw;
            }
        }
        if (tid < 16) keepw_s[tid] = kw;
    }
    __syncthreads();

    int kept = (keepw_s[tid >> 5] >> (tid & 31)) & 1;
    int gr = b * NN + tid;
    int go = b * NN + gs_ord[gr];
    g_keep[go] = kept;

    float4 sb = gs_box[gr];
    float* ob = out + (size_t)BB * NN * POOL_PER_BOX;
    float* ok = ob + (size_t)BB * NN * 4;
    ob[go * 4 + 0] = kept ? sb.x : 0.0f;
    ob[go * 4 + 1] = kept ? sb.y : 0.0f;
    ob[go * 4 + 2] = kept ? sb.z : 0.0f;
    ob[go * 4 + 3] = kept ? sb.w : 0.0f;
    ok[go] = kept ? 1.0f : 0.0f;
}

// ---------------------------------------------------------------------------
// Kernel 2: ROI align. One block per box; thread t < 196 owns one output
// position; 16 offsets + 16 pre-scaled weights in registers; channel loop.
// ---------------------------------------------------------------------------
__global__ __launch_bounds__(256, 3) void pool_kernel(const float* __restrict__ p4,
                                                      const float* __restrict__ p8,
                                                      const float* __restrict__ p16,
                                                      const float* __restrict__ p32,
                                                      float* __restrict__ out)
{
    const int bn  = blockIdx.x;
    const int b   = bn / NN;
    const int tid = threadIdx.x;

    float* o = out + (size_t)bn * POOL_PER_BOX;

    if (!g_keep[bn]) {
        float4* o4 = (float4*)o;
        float4 z = make_float4(0.f, 0.f, 0.f, 0.f);
        #pragma unroll 4
        for (int i = tid; i < POOL_PER_BOX / 4; i += 256) o4[i] = z;
        return;
    }
    if (tid >= NPOS) return;

    const int lev = g_level[bn];
    const float* feat;
    int H;
    float stride;
    if (lev == 1)      { feat = p4;  H = 256; stride = 4.0f;  }
    else if (lev == 2) { feat = p8;  H = 128; stride = 8.0f;  }
    else if (lev == 3) { feat = p16; H = 64;  stride = 16.0f; }
    else               { feat = p32; H = 32;  stride = 32.0f; }
    const int W  = H;
    const int HW = H * W;

    float inv = 1.0f / stride;
    float rx1 = g_verts[bn * 4 + 0] * inv;
    float ry1 = g_verts[bn * 4 + 1] * inv;
    float rx2 = g_verts[bn * 4 + 2] * inv;
    float ry2 = g_verts[bn * 4 + 3] * inv;
    float bw = (rx2 - rx1) / (float)OUTSZ;
    float bh = (ry2 - ry1) / (float)OUTSZ;

    const int oy = tid / OUTSZ;
    const int ox = tid - oy * OUTSZ;

    int   cofs[4];
    float wx[4];
    #pragma unroll
    for (int j = 0; j < 2; j++) {
        float g  = ((float)(2 * ox + j) + 0.5f) * 0.5f;
        float xs = fminf(fmaxf(rx1 + g * bw, 0.0f), (float)W - 1.0f);
        float x0f = floorf(xs);
        int   x0  = (int)x0f;
        float lx  = xs - x0f;
        cofs[2 * j]     = x0;
        cofs[2 * j + 1] = min(x0 + 1, W - 1);
        wx[2 * j]       = 1.0f - lx;
        wx[2 * j + 1]   = lx;
    }
    int   rofs[4];
    float wy[4];
    #pragma unroll
    for (int j = 0; j < 2; j++) {
        float g  = ((float)(2 * oy + j) + 0.5f) * 0.5f;
        float ys = fminf(fmaxf(ry1 + g * bh, 0.0f), (float)H - 1.0f);
        float y0f = floorf(ys);
        int   y0  = (int)y0f;
        float ly  = ys - y0f;
        rofs[2 * j]     = y0 * W;
        rofs[2 * j + 1] = min(y0 + 1, H - 1) * W;
        wy[2 * j]       = 0.25f * (1.0f - ly);
        wy[2 * j + 1]   = 0.25f * ly;
    }

    int   off[16];
    float wxy[16];
    #pragma unroll
    for (int k = 0; k < 4; k++)
        #pragma unroll
        for (int l = 0; l < 4; l++) {
            off[k * 4 + l] = rofs[k] + cofs[l];
            wxy[k * 4 + l] = wy[k] * wx[l];
        }

    const float* fp = feat + (size_t)b * CC * HW;
    float* op = o + tid;

    #pragma unroll 1
    for (int c = 0; c < CC; c++) {
        float a0 = wxy[0]  * __ldg(fp + off[0]);
        float a1 = wxy[1]  * __ldg(fp + off[1]);
        float a2 = wxy[2]  * __ldg(fp + off[2]);
        float a3 = wxy[3]  * __ldg(fp + off[3]);
        a0 = fmaf(wxy[4],  __ldg(fp + off[4]),  a0);
        a1 = fmaf(wxy[5],  __ldg(fp + off[5]),  a1);
        a2 = fmaf(wxy[6],  __ldg(fp + off[6]),  a2);
        a3 = fmaf(wxy[7],  __ldg(fp + off[7]),  a3);
        a0 = fmaf(wxy[8],  __ldg(fp + off[8]),  a0);
        a1 = fmaf(wxy[9],  __ldg(fp + off[9]),  a1);
        a2 = fmaf(wxy[10], __ldg(fp + off[10]), a2);
        a3 = fmaf(wxy[11], __ldg(fp + off[11]), a3);
        a0 = fmaf(wxy[12], __ldg(fp + off[12]), a0);
        a1 = fmaf(wxy[13], __ldg(fp + off[13]), a1);
        a2 = fmaf(wxy[14], __ldg(fp + off[14]), a2);
        a3 = fmaf(wxy[15], __ldg(fp + off[15]), a3);
        op[c * NPOS] = (a0 + a1) + (a2 + a3);
        fp += HW;
    }
}

extern "C" void kernel_launch(void* const* d_in, const int* in_sizes, int n_in,
                              void* d_out, int out_size)
{
    const float* p4     = (const float*)d_in[0];
    const float* p8     = (const float*)d_in[1];
    const float* p16    = (const float*)d_in[2];
    const float* p32    = (const float*)d_in[3];
    const float* boxes  = (const float*)d_in[4];
    const float* scores = (const float*)d_in[5];
    float* out = (float*)d_out;

    nms_sort_kernel<<<BB, NN>>>(boxes, scores);
    nms_mask_kernel<<<BB * 4, 128>>>();
    nms_scan_kernel<<<BB, NN>>>(out);
    pool_kernel<<<BB * NN, 256>>>(p4, p8, p16, p32, out);
}